// round 1
// baseline (speedup 1.0000x reference)
#include <cuda_runtime.h>
#include <math.h>
#include <float.h>

// Problem constants
#define Bn   4
#define Dd   256
#define Nn   2048
#define Mm   2048
#define Hh   4
#define DIMh 64

// Scratch (allocation-free: __device__ globals)
__device__ float g_q[Bn * Dd * Nn];
__device__ float g_k[Bn * Dd * Mm];
__device__ float g_v[Bn * Dd * Mm];
__device__ float g_msg[Bn * Dd * Nn];
__device__ float g_message[Bn * Dd * Nn];
__device__ float g_h[Bn * 2 * Dd * Nn];
__device__ float g_scores[(size_t)Bn * Hh * Nn * Mm];   // 268 MB

// ---------------------------------------------------------------------------
// Generic per-batch 1x1-conv GEMM: Y[b,o,n] = sum_c W[o,c] * X[b,c,n] + bias[o]
// Optional concat input (c<INC/2 from X0, else X1) and BN+ReLU epilogue.
// Tile: 64(o) x 64(n), K-chunk 16, 256 threads, 4x4 microtile.
// ---------------------------------------------------------------------------
template<int OUTC, int INC, bool CONCAT, bool BNRELU>
__global__ void gemm_proj(const float* __restrict__ W, const float* __restrict__ bias,
                          const float* __restrict__ X0, const float* __restrict__ X1,
                          float* __restrict__ Y,
                          const float* __restrict__ gamma, const float* __restrict__ beta,
                          const float* __restrict__ rmean, const float* __restrict__ rvar)
{
    const int tx = threadIdx.x, ty = threadIdx.y;
    const int tid = ty * 16 + tx;
    const int n0 = blockIdx.x * 64;
    const int o0 = blockIdx.y * 64;
    const int b  = blockIdx.z;
    const int XC = CONCAT ? (INC / 2) : INC;
    const float* x0 = X0 + (size_t)b * XC * Nn;
    const float* x1 = CONCAT ? (X1 + (size_t)b * XC * Nn) : nullptr;

    __shared__ float Ws[16][68];
    __shared__ float Xs[16][68];

    float acc[4][4] = {};

    for (int c0 = 0; c0 < INC; c0 += 16) {
        // Load W tile: Ws[kk][oo] = W[o0+oo, c0+kk]
        {
            int kk = tid & 15, oo = tid >> 4;
            #pragma unroll
            for (int r = 0; r < 4; r++)
                Ws[kk][oo + 16 * r] = W[(size_t)(o0 + oo + 16 * r) * INC + c0 + kk];
        }
        // Load X tile: Xs[kk][nn] = X[b, c0+kk, n0+nn]
        {
            int nn = tid & 63, kb = tid >> 6;
            #pragma unroll
            for (int r = 0; r < 4; r++) {
                int kk = kb + 4 * r;
                int c  = c0 + kk;
                float val;
                if (!CONCAT || c < INC / 2) val = x0[(size_t)c * Nn + n0 + nn];
                else                        val = x1[(size_t)(c - INC / 2) * Nn + n0 + nn];
                Xs[kk][nn] = val;
            }
        }
        __syncthreads();
        #pragma unroll
        for (int kk = 0; kk < 16; kk++) {
            float a[4], bb[4];
            #pragma unroll
            for (int i = 0; i < 4; i++) a[i] = Ws[kk][ty * 4 + i];
            #pragma unroll
            for (int j = 0; j < 4; j++) bb[j] = Xs[kk][tx * 4 + j];
            #pragma unroll
            for (int i = 0; i < 4; i++)
                #pragma unroll
                for (int j = 0; j < 4; j++)
                    acc[i][j] = fmaf(a[i], bb[j], acc[i][j]);
        }
        __syncthreads();
    }

    #pragma unroll
    for (int i = 0; i < 4; i++) {
        int o = o0 + ty * 4 + i;
        float bv = bias[o];
        float sc = 1.f, sh = 0.f;
        if (BNRELU) {
            float rs = rsqrtf(rvar[o] + 1e-3f);
            sc = gamma[o] * rs;
            sh = beta[o] - rmean[o] * sc;
        }
        #pragma unroll
        for (int j = 0; j < 4; j++) {
            int n = n0 + tx * 4 + j;
            float t = acc[i][j] + bv;
            if (BNRELU) t = fmaxf(t * sc + sh, 0.f);
            Y[(size_t)b * OUTC * Nn + (size_t)o * Nn + n] = t;
        }
    }
}

// ---------------------------------------------------------------------------
// Attention scores: S[bh, n, m] = (1/8) * sum_d q[b, d*4+h, n] * k[b, d*4+h, m]
// masked -> -FLT_MAX. Tile 64(n) x 64(m), K = 64 dims.
// ---------------------------------------------------------------------------
__global__ void attn_scores(const float* __restrict__ mask)
{
    const int tx = threadIdx.x, ty = threadIdx.y;
    const int tid = ty * 16 + tx;
    const int m0 = blockIdx.x * 64;
    const int n0 = blockIdx.y * 64;
    const int bh = blockIdx.z;
    const int b = bh / Hh, h = bh % Hh;
    const float* q = g_q + (size_t)b * Dd * Nn;
    const float* k = g_k + (size_t)b * Dd * Mm;

    __shared__ float Qs[16][68];
    __shared__ float Ks[16][68];

    float acc[4][4] = {};

    for (int c0 = 0; c0 < DIMh; c0 += 16) {
        {
            int nn = tid & 63, kb = tid >> 6;
            #pragma unroll
            for (int r = 0; r < 4; r++) {
                int kk = kb + 4 * r;
                int ch = (c0 + kk) * Hh + h;
                Qs[kk][nn] = q[(size_t)ch * Nn + n0 + nn];
                Ks[kk][nn] = k[(size_t)ch * Mm + m0 + nn];
            }
        }
        __syncthreads();
        #pragma unroll
        for (int kk = 0; kk < 16; kk++) {
            float a[4], bb[4];
            #pragma unroll
            for (int i = 0; i < 4; i++) a[i] = Qs[kk][ty * 4 + i];
            #pragma unroll
            for (int j = 0; j < 4; j++) bb[j] = Ks[kk][tx * 4 + j];
            #pragma unroll
            for (int i = 0; i < 4; i++)
                #pragma unroll
                for (int j = 0; j < 4; j++)
                    acc[i][j] = fmaf(a[i], bb[j], acc[i][j]);
        }
        __syncthreads();
    }

    #pragma unroll
    for (int i = 0; i < 4; i++) {
        int n = n0 + ty * 4 + i;
        #pragma unroll
        for (int j = 0; j < 4; j++) {
            int m = m0 + tx * 4 + j;
            float mv = mask[((size_t)b * Nn + n) * Mm + m];
            float s  = (mv > 0.f) ? (acc[i][j] * 0.125f) : -FLT_MAX;
            g_scores[((size_t)bh * Nn + n) * Mm + m] = s;
        }
    }
}

// ---------------------------------------------------------------------------
// Row-wise softmax over M=2048 in-place on g_scores. One block per row.
// ---------------------------------------------------------------------------
__global__ void softmax_rows()
{
    const int row = blockIdx.x;
    float* p = g_scores + (size_t)row * Mm;
    const int tid = threadIdx.x;          // 256 threads
    __shared__ float red[256];

    float v[8];
    float mx = -FLT_MAX;
    #pragma unroll
    for (int r = 0; r < 8; r++) {
        v[r] = p[tid + 256 * r];
        mx = fmaxf(mx, v[r]);
    }
    red[tid] = mx;
    __syncthreads();
    for (int s = 128; s > 0; s >>= 1) {
        if (tid < s) red[tid] = fmaxf(red[tid], red[tid + s]);
        __syncthreads();
    }
    mx = red[0];
    __syncthreads();

    float sum = 0.f;
    #pragma unroll
    for (int r = 0; r < 8; r++) {
        v[r] = __expf(v[r] - mx);
        sum += v[r];
    }
    red[tid] = sum;
    __syncthreads();
    for (int s = 128; s > 0; s >>= 1) {
        if (tid < s) red[tid] += red[tid + s];
        __syncthreads();
    }
    float inv = 1.f / red[0];
    #pragma unroll
    for (int r = 0; r < 8; r++)
        p[tid + 256 * r] = v[r] * inv;
}

// ---------------------------------------------------------------------------
// PV: msg[b, d*4+h, n] = sum_m P[bh, n, m] * v[b, d*4+h, m]
// Tile: 64(d) x 64(n), K = M in chunks of 16.
// ---------------------------------------------------------------------------
__global__ void attn_pv()
{
    const int tx = threadIdx.x, ty = threadIdx.y;
    const int tid = ty * 16 + tx;
    const int n0 = blockIdx.x * 64;
    const int bh = blockIdx.z;
    const int b = bh / Hh, h = bh % Hh;
    const float* v = g_v + (size_t)b * Dd * Mm;
    const float* P = g_scores + (size_t)bh * Nn * Mm;

    __shared__ float Vs[16][68];
    __shared__ float Ps[16][68];

    float acc[4][4] = {};

    for (int m0 = 0; m0 < Mm; m0 += 16) {
        {
            int kk = tid & 15, base = tid >> 4;
            #pragma unroll
            for (int r = 0; r < 4; r++) {
                int dd = base + 16 * r;
                Vs[kk][dd] = v[(size_t)(dd * Hh + h) * Mm + m0 + kk];
                Ps[kk][dd] = P[(size_t)(n0 + dd) * Mm + m0 + kk];
            }
        }
        __syncthreads();
        #pragma unroll
        for (int kk = 0; kk < 16; kk++) {
            float a[4], bb[4];
            #pragma unroll
            for (int i = 0; i < 4; i++) a[i] = Vs[kk][ty * 4 + i];
            #pragma unroll
            for (int j = 0; j < 4; j++) bb[j] = Ps[kk][tx * 4 + j];
            #pragma unroll
            for (int i = 0; i < 4; i++)
                #pragma unroll
                for (int j = 0; j < 4; j++)
                    acc[i][j] = fmaf(a[i], bb[j], acc[i][j]);
        }
        __syncthreads();
    }

    #pragma unroll
    for (int i = 0; i < 4; i++) {
        int d = ty * 4 + i;
        #pragma unroll
        for (int j = 0; j < 4; j++) {
            int n = n0 + tx * 4 + j;
            g_msg[((size_t)b * Dd + d * Hh + h) * Nn + n] = acc[i][j];
        }
    }
}

// ---------------------------------------------------------------------------
extern "C" void kernel_launch(void* const* d_in, const int* in_sizes, int n_in,
                              void* d_out, int out_size)
{
    const float* x      = (const float*)d_in[0];
    const float* source = (const float*)d_in[1];
    const float* mask   = (const float*)d_in[2];
    const float* Wq = (const float*)d_in[3];
    const float* bq = (const float*)d_in[4];
    const float* Wk = (const float*)d_in[5];
    const float* bk = (const float*)d_in[6];
    const float* Wv = (const float*)d_in[7];
    const float* bv = (const float*)d_in[8];
    const float* Wm = (const float*)d_in[9];
    const float* bm = (const float*)d_in[10];
    const float* W1 = (const float*)d_in[11];
    const float* b1 = (const float*)d_in[12];
    const float* gamma = (const float*)d_in[13];
    const float* beta  = (const float*)d_in[14];
    const float* rmean = (const float*)d_in[15];
    const float* rvar  = (const float*)d_in[16];
    const float* W2 = (const float*)d_in[17];
    const float* b2 = (const float*)d_in[18];
    float* out = (float*)d_out;

    float *qb, *kb, *vb, *msgb, *messageb, *hb;
    cudaGetSymbolAddress((void**)&qb, g_q);
    cudaGetSymbolAddress((void**)&kb, g_k);
    cudaGetSymbolAddress((void**)&vb, g_v);
    cudaGetSymbolAddress((void**)&msgb, g_msg);
    cudaGetSymbolAddress((void**)&messageb, g_message);
    cudaGetSymbolAddress((void**)&hb, g_h);

    dim3 thr(16, 16);

    // q, k, v projections
    gemm_proj<256, 256, false, false><<<dim3(32, 4, 4), thr>>>(
        Wq, bq, x, nullptr, qb, nullptr, nullptr, nullptr, nullptr);
    gemm_proj<256, 256, false, false><<<dim3(32, 4, 4), thr>>>(
        Wk, bk, source, nullptr, kb, nullptr, nullptr, nullptr, nullptr);
    gemm_proj<256, 256, false, false><<<dim3(32, 4, 4), thr>>>(
        Wv, bv, source, nullptr, vb, nullptr, nullptr, nullptr, nullptr);

    // attention
    attn_scores<<<dim3(32, 32, 16), thr>>>(mask);
    softmax_rows<<<Bn * Hh * Nn, 256>>>();
    attn_pv<<<dim3(32, 1, 16), thr>>>();

    // message projection
    gemm_proj<256, 256, false, false><<<dim3(32, 4, 4), thr>>>(
        Wm, bm, msgb, nullptr, messageb, nullptr, nullptr, nullptr, nullptr);

    // MLP layer 1 (concat[x, message]) + BN + ReLU
    gemm_proj<512, 512, true, true><<<dim3(32, 8, 4), thr>>>(
        W1, b1, x, messageb, hb, gamma, beta, rmean, rvar);

    // MLP layer 2 -> output
    gemm_proj<256, 512, false, false><<<dim3(32, 4, 4), thr>>>(
        W2, b2, hb, nullptr, out, nullptr, nullptr, nullptr, nullptr);
}

// round 5
// speedup vs baseline: 1.2566x; 1.2566x over previous
#include <cuda_runtime.h>
#include <math.h>
#include <float.h>
#include <stdint.h>

// Problem constants
#define Bn   4
#define Dd   256
#define Nn   2048
#define Mm   2048
#define Hh   4
#define DIMh 64

// Scratch (allocation-free: __device__ globals)
__device__ float g_q[Bn * Dd * Nn];
__device__ float g_k[Bn * Dd * Mm];
__device__ float g_v[Bn * Dd * Mm];
__device__ float g_msg[Bn * Dd * Nn];
__device__ float g_message[Bn * Dd * Nn];
__device__ float g_h[Bn * 2 * Dd * Nn];
__device__ float g_scores[(size_t)Bn * Hh * Nn * Mm];   // 268 MB

// ---------------------------------------------------------------------------
// tf32 helpers
// ---------------------------------------------------------------------------
__device__ __forceinline__ uint32_t f2tf(float x)
{
    uint32_t r;
    asm("cvt.rna.tf32.f32 %0, %1;" : "=r"(r) : "f"(x));
    return r;
}
// 3xTF32 split: x = hi + lo (both tf32-representable)
__device__ __forceinline__ void split_tf32(float x, uint32_t& hi, uint32_t& lo)
{
    hi = f2tf(x);
    lo = f2tf(x - __uint_as_float(hi));
}

__device__ __forceinline__ void mma_tf32(float (&d)[4],
                                         uint32_t a0, uint32_t a1, uint32_t a2, uint32_t a3,
                                         uint32_t b0, uint32_t b1)
{
    asm volatile(
        "mma.sync.aligned.m16n8k8.row.col.f32.tf32.tf32.f32 "
        "{%0,%1,%2,%3}, {%4,%5,%6,%7}, {%8,%9}, {%0,%1,%2,%3};\n"
        : "+f"(d[0]), "+f"(d[1]), "+f"(d[2]), "+f"(d[3])
        : "r"(a0), "r"(a1), "r"(a2), "r"(a3), "r"(b0), "r"(b1));
}

// 3-term compensated mma: acc += (Ah+Al)*(Bh+Bl) - Al*Bl
__device__ __forceinline__ void mma3(float (&d)[4],
                                     const uint32_t (&ah)[4], const uint32_t (&al)[4],
                                     const uint32_t (&bh)[2], const uint32_t (&bl)[2])
{
    mma_tf32(d, al[0], al[1], al[2], al[3], bh[0], bh[1]);
    mma_tf32(d, ah[0], ah[1], ah[2], ah[3], bl[0], bl[1]);
    mma_tf32(d, ah[0], ah[1], ah[2], ah[3], bh[0], bh[1]);
}

#define SM_STRIDE 136   // words; 136 % 32 == 8 -> conflict-free fragment loads
#define PV_STRIDE 72

// ---------------------------------------------------------------------------
// Generic per-batch 1x1-conv GEMM via 3xTF32 mma:
//   Y[b,o,n] = sum_c W[o,c] * X[b,c,n] + bias[o]
// Block tile 128(o) x 128(n), K-chunk 32, 256 threads = 8 warps (2x4),
// warp tile 64x32. Dynamic smem: 4 tiles of [32][SM_STRIDE] u32 (hi/lo A/B).
// ---------------------------------------------------------------------------
template<int OUTC, int INC, bool CONCAT, bool BNRELU>
__global__ void __launch_bounds__(256)
gemm_mma(const float* __restrict__ W, const float* __restrict__ bias,
         const float* __restrict__ X0, const float* __restrict__ X1,
         float* __restrict__ Y,
         const float* __restrict__ gamma, const float* __restrict__ beta,
         const float* __restrict__ rmean, const float* __restrict__ rvar)
{
    extern __shared__ uint32_t dsm[];
    uint32_t (*AsH)[SM_STRIDE] = (uint32_t(*)[SM_STRIDE])(dsm);
    uint32_t (*AsL)[SM_STRIDE] = (uint32_t(*)[SM_STRIDE])(dsm + 32 * SM_STRIDE);
    uint32_t (*BsH)[SM_STRIDE] = (uint32_t(*)[SM_STRIDE])(dsm + 64 * SM_STRIDE);
    uint32_t (*BsL)[SM_STRIDE] = (uint32_t(*)[SM_STRIDE])(dsm + 96 * SM_STRIDE);

    const int tid = threadIdx.x;
    const int n0 = blockIdx.x * 128;
    const int o0 = blockIdx.y * 128;
    const int b  = blockIdx.z;
    const int XC = CONCAT ? (INC / 2) : INC;
    const float* x0 = X0 + (size_t)b * XC * Nn;
    const float* x1 = CONCAT ? (X1 + (size_t)b * XC * Nn) : nullptr;

    const int w      = tid >> 5;
    const int lane   = tid & 31;
    const int g      = lane >> 2;
    const int tg     = lane & 3;
    const int warp_m = w >> 2;
    const int warp_n = w & 3;

    float acc[4][4][4] = {};

    const int a_row  = tid >> 1;
    const int a_half = tid & 1;
    const int b_row  = tid >> 3;
    const int b_col  = (tid & 7) * 16;

    for (int c0 = 0; c0 < INC; c0 += 32) {
        // --- load W tile (transposed store, split) ---
        {
            const float* wp = W + (size_t)(o0 + a_row) * INC + c0 + a_half * 16;
            #pragma unroll
            for (int q = 0; q < 4; q++) {
                float4 v4 = *(const float4*)(wp + q * 4);
                int cl = a_half * 16 + q * 4;
                uint32_t h0,l0,h1,l1,h2,l2,h3,l3;
                split_tf32(v4.x, h0, l0); split_tf32(v4.y, h1, l1);
                split_tf32(v4.z, h2, l2); split_tf32(v4.w, h3, l3);
                AsH[cl+0][a_row]=h0; AsL[cl+0][a_row]=l0;
                AsH[cl+1][a_row]=h1; AsL[cl+1][a_row]=l1;
                AsH[cl+2][a_row]=h2; AsL[cl+2][a_row]=l2;
                AsH[cl+3][a_row]=h3; AsL[cl+3][a_row]=l3;
            }
        }
        // --- load X tile (direct store, split) ---
        {
            int c = c0 + b_row;
            const float* xp;
            if (!CONCAT || c < INC / 2) xp = x0 + (size_t)c * Nn + n0 + b_col;
            else                        xp = x1 + (size_t)(c - INC / 2) * Nn + n0 + b_col;
            #pragma unroll
            for (int q = 0; q < 4; q++) {
                float4 v4 = *(const float4*)(xp + q * 4);
                int cc = b_col + q * 4;
                uint32_t h,l;
                split_tf32(v4.x, h, l); BsH[b_row][cc+0]=h; BsL[b_row][cc+0]=l;
                split_tf32(v4.y, h, l); BsH[b_row][cc+1]=h; BsL[b_row][cc+1]=l;
                split_tf32(v4.z, h, l); BsH[b_row][cc+2]=h; BsL[b_row][cc+2]=l;
                split_tf32(v4.w, h, l); BsH[b_row][cc+3]=h; BsL[b_row][cc+3]=l;
            }
        }
        __syncthreads();

        #pragma unroll
        for (int ks = 0; ks < 4; ks++) {
            const int kb = ks * 8;
            uint32_t ah[4][4], al[4][4], bh[4][2], bl[4][2];
            #pragma unroll
            for (int mt = 0; mt < 4; mt++) {
                int m = warp_m * 64 + mt * 16;
                ah[mt][0]=AsH[kb+tg  ][m+g  ]; al[mt][0]=AsL[kb+tg  ][m+g  ];
                ah[mt][1]=AsH[kb+tg  ][m+g+8]; al[mt][1]=AsL[kb+tg  ][m+g+8];
                ah[mt][2]=AsH[kb+tg+4][m+g  ]; al[mt][2]=AsL[kb+tg+4][m+g  ];
                ah[mt][3]=AsH[kb+tg+4][m+g+8]; al[mt][3]=AsL[kb+tg+4][m+g+8];
            }
            #pragma unroll
            for (int nt = 0; nt < 4; nt++) {
                int n = warp_n * 32 + nt * 8 + g;
                bh[nt][0]=BsH[kb+tg  ][n]; bl[nt][0]=BsL[kb+tg  ][n];
                bh[nt][1]=BsH[kb+tg+4][n]; bl[nt][1]=BsL[kb+tg+4][n];
            }
            #pragma unroll
            for (int mt = 0; mt < 4; mt++)
                #pragma unroll
                for (int nt = 0; nt < 4; nt++)
                    mma3(acc[mt][nt], ah[mt], al[mt], bh[nt], bl[nt]);
        }
        __syncthreads();
    }

    // --- epilogue ---
    float* yb = Y + (size_t)b * OUTC * Nn;
    #pragma unroll
    for (int mt = 0; mt < 4; mt++) {
        int r0 = o0 + warp_m * 64 + mt * 16 + g;
        int r1 = r0 + 8;
        float bv0 = bias[r0], bv1 = bias[r1];
        float sc0 = 1.f, sh0 = 0.f, sc1 = 1.f, sh1 = 0.f;
        if (BNRELU) {
            float rs0 = rsqrtf(rvar[r0] + 1e-3f);
            sc0 = gamma[r0] * rs0; sh0 = beta[r0] - rmean[r0] * sc0;
            float rs1 = rsqrtf(rvar[r1] + 1e-3f);
            sc1 = gamma[r1] * rs1; sh1 = beta[r1] - rmean[r1] * sc1;
        }
        #pragma unroll
        for (int nt = 0; nt < 4; nt++) {
            int n = n0 + warp_n * 32 + nt * 8 + 2 * tg;
            float t0 = acc[mt][nt][0] + bv0;
            float t1 = acc[mt][nt][1] + bv0;
            float t2 = acc[mt][nt][2] + bv1;
            float t3 = acc[mt][nt][3] + bv1;
            if (BNRELU) {
                t0 = fmaxf(t0 * sc0 + sh0, 0.f);
                t1 = fmaxf(t1 * sc0 + sh0, 0.f);
                t2 = fmaxf(t2 * sc1 + sh1, 0.f);
                t3 = fmaxf(t3 * sc1 + sh1, 0.f);
            }
            *(float2*)&yb[(size_t)r0 * Nn + n] = make_float2(t0, t1);
            *(float2*)&yb[(size_t)r1 * Nn + n] = make_float2(t2, t3);
        }
    }
}

// ---------------------------------------------------------------------------
// Attention scores via 3xTF32 mma:
//   S[bh,n,m] = (1/8) * sum_d q[b,d*4+h,n] * k[b,d*4+h,m], masked -> -FLT_MAX
// ---------------------------------------------------------------------------
__global__ void __launch_bounds__(256)
attn_scores_mma(const float* __restrict__ mask)
{
    extern __shared__ uint32_t dsm[];
    uint32_t (*QsH)[SM_STRIDE] = (uint32_t(*)[SM_STRIDE])(dsm);
    uint32_t (*QsL)[SM_STRIDE] = (uint32_t(*)[SM_STRIDE])(dsm + 32 * SM_STRIDE);
    uint32_t (*KsH)[SM_STRIDE] = (uint32_t(*)[SM_STRIDE])(dsm + 64 * SM_STRIDE);
    uint32_t (*KsL)[SM_STRIDE] = (uint32_t(*)[SM_STRIDE])(dsm + 96 * SM_STRIDE);

    const int tid = threadIdx.x;
    const int m0 = blockIdx.x * 128;
    const int n0 = blockIdx.y * 128;
    const int bh = blockIdx.z;
    const int b = bh >> 2, h = bh & 3;
    const float* q = g_q + (size_t)b * Dd * Nn;
    const float* k = g_k + (size_t)b * Dd * Mm;

    const int w      = tid >> 5;
    const int lane   = tid & 31;
    const int g      = lane >> 2;
    const int tg     = lane & 3;
    const int warp_m = w >> 2;
    const int warp_n = w & 3;

    float acc[4][4][4] = {};

    const int l_row = tid >> 3;
    const int l_col = (tid & 7) * 16;

    for (int c0 = 0; c0 < DIMh; c0 += 32) {
        int ch = (c0 + l_row) * Hh + h;
        const float* qp = q + (size_t)ch * Nn + n0 + l_col;
        const float* kp = k + (size_t)ch * Mm + m0 + l_col;
        #pragma unroll
        for (int qq = 0; qq < 4; qq++) {
            float4 vq = *(const float4*)(qp + qq * 4);
            float4 vk = *(const float4*)(kp + qq * 4);
            int cc = l_col + qq * 4;
            uint32_t hh, ll;
            split_tf32(vq.x, hh, ll); QsH[l_row][cc+0]=hh; QsL[l_row][cc+0]=ll;
            split_tf32(vq.y, hh, ll); QsH[l_row][cc+1]=hh; QsL[l_row][cc+1]=ll;
            split_tf32(vq.z, hh, ll); QsH[l_row][cc+2]=hh; QsL[l_row][cc+2]=ll;
            split_tf32(vq.w, hh, ll); QsH[l_row][cc+3]=hh; QsL[l_row][cc+3]=ll;
            split_tf32(vk.x, hh, ll); KsH[l_row][cc+0]=hh; KsL[l_row][cc+0]=ll;
            split_tf32(vk.y, hh, ll); KsH[l_row][cc+1]=hh; KsL[l_row][cc+1]=ll;
            split_tf32(vk.z, hh, ll); KsH[l_row][cc+2]=hh; KsL[l_row][cc+2]=ll;
            split_tf32(vk.w, hh, ll); KsH[l_row][cc+3]=hh; KsL[l_row][cc+3]=ll;
        }
        __syncthreads();

        #pragma unroll
        for (int ks = 0; ks < 4; ks++) {
            const int kb = ks * 8;
            uint32_t ah[4][4], al[4][4], bh2[4][2], bl2[4][2];
            #pragma unroll
            for (int mt = 0; mt < 4; mt++) {
                int n = warp_m * 64 + mt * 16;
                ah[mt][0]=QsH[kb+tg  ][n+g  ]; al[mt][0]=QsL[kb+tg  ][n+g  ];
                ah[mt][1]=QsH[kb+tg  ][n+g+8]; al[mt][1]=QsL[kb+tg  ][n+g+8];
                ah[mt][2]=QsH[kb+tg+4][n+g  ]; al[mt][2]=QsL[kb+tg+4][n+g  ];
                ah[mt][3]=QsH[kb+tg+4][n+g+8]; al[mt][3]=QsL[kb+tg+4][n+g+8];
            }
            #pragma unroll
            for (int nt = 0; nt < 4; nt++) {
                int m = warp_n * 32 + nt * 8 + g;
                bh2[nt][0]=KsH[kb+tg  ][m]; bl2[nt][0]=KsL[kb+tg  ][m];
                bh2[nt][1]=KsH[kb+tg+4][m]; bl2[nt][1]=KsL[kb+tg+4][m];
            }
            #pragma unroll
            for (int mt = 0; mt < 4; mt++)
                #pragma unroll
                for (int nt = 0; nt < 4; nt++)
                    mma3(acc[mt][nt], ah[mt], al[mt], bh2[nt], bl2[nt]);
        }
        __syncthreads();
    }

    float* sp = g_scores + (size_t)bh * Nn * Mm;
    #pragma unroll
    for (int mt = 0; mt < 4; mt++) {
        int nr0 = n0 + warp_m * 64 + mt * 16 + g;
        int nr1 = nr0 + 8;
        #pragma unroll
        for (int nt = 0; nt < 4; nt++) {
            int m = m0 + warp_n * 32 + nt * 8 + 2 * tg;
            float2 mk0 = *(const float2*)&mask[((size_t)b * Nn + nr0) * Mm + m];
            float2 mk1 = *(const float2*)&mask[((size_t)b * Nn + nr1) * Mm + m];
            float s0 = (mk0.x > 0.f) ? acc[mt][nt][0] * 0.125f : -FLT_MAX;
            float s1 = (mk0.y > 0.f) ? acc[mt][nt][1] * 0.125f : -FLT_MAX;
            float s2 = (mk1.x > 0.f) ? acc[mt][nt][2] * 0.125f : -FLT_MAX;
            float s3 = (mk1.y > 0.f) ? acc[mt][nt][3] * 0.125f : -FLT_MAX;
            *(float2*)&sp[(size_t)nr0 * Mm + m] = make_float2(s0, s1);
            *(float2*)&sp[(size_t)nr1 * Mm + m] = make_float2(s2, s3);
        }
    }
}

// ---------------------------------------------------------------------------
// Row-wise softmax over M=2048 in-place on g_scores. One block per row.
// ---------------------------------------------------------------------------
__global__ void __launch_bounds__(256)
softmax_rows()
{
    const int row = blockIdx.x;
    float4* p = (float4*)(g_scores + (size_t)row * Mm);
    const int tid = threadIdx.x;
    __shared__ float red[256];

    float4 v[2];
    float mx = -FLT_MAX;
    #pragma unroll
    for (int r = 0; r < 2; r++) {
        v[r] = p[tid + 256 * r];
        mx = fmaxf(mx, fmaxf(fmaxf(v[r].x, v[r].y), fmaxf(v[r].z, v[r].w)));
    }
    red[tid] = mx;
    __syncthreads();
    for (int s = 128; s > 0; s >>= 1) {
        if (tid < s) red[tid] = fmaxf(red[tid], red[tid + s]);
        __syncthreads();
    }
    mx = red[0];
    __syncthreads();

    float sum = 0.f;
    #pragma unroll
    for (int r = 0; r < 2; r++) {
        v[r].x = __expf(v[r].x - mx);
        v[r].y = __expf(v[r].y - mx);
        v[r].z = __expf(v[r].z - mx);
        v[r].w = __expf(v[r].w - mx);
        sum += v[r].x + v[r].y + v[r].z + v[r].w;
    }
    red[tid] = sum;
    __syncthreads();
    for (int s = 128; s > 0; s >>= 1) {
        if (tid < s) red[tid] += red[tid + s];
        __syncthreads();
    }
    float inv = 1.f / red[0];
    #pragma unroll
    for (int r = 0; r < 2; r++) {
        v[r].x *= inv; v[r].y *= inv; v[r].z *= inv; v[r].w *= inv;
        p[tid + 256 * r] = v[r];
    }
}

// ---------------------------------------------------------------------------
// PV via 3xTF32 mma:
//   msg[b, d*4+h, n] = sum_m P[bh,n,m] * v[b, d*4+h, m]
// Block tile 64(d) x 128(n); warp tile 32x32.
// ---------------------------------------------------------------------------
__global__ void __launch_bounds__(256)
attn_pv_mma()
{
    extern __shared__ uint32_t dsm[];
    uint32_t (*AsH)[PV_STRIDE] = (uint32_t(*)[PV_STRIDE])(dsm);
    uint32_t (*AsL)[PV_STRIDE] = (uint32_t(*)[PV_STRIDE])(dsm + 32 * PV_STRIDE);
    uint32_t (*BsH)[SM_STRIDE] = (uint32_t(*)[SM_STRIDE])(dsm + 64 * PV_STRIDE);
    uint32_t (*BsL)[SM_STRIDE] = (uint32_t(*)[SM_STRIDE])(dsm + 64 * PV_STRIDE + 32 * SM_STRIDE);

    const int tid = threadIdx.x;
    const int n0 = blockIdx.x * 128;
    const int bh = blockIdx.z;
    const int b = bh >> 2, h = bh & 3;
    const float* v = g_v + (size_t)b * Dd * Mm;
    const float* P = g_scores + (size_t)bh * Nn * Mm;

    const int w      = tid >> 5;
    const int lane   = tid & 31;
    const int g      = lane >> 2;
    const int tg     = lane & 3;
    const int warp_m = w >> 2;
    const int warp_n = w & 3;

    float acc[2][4][4] = {};

    const int va_d  = tid >> 2;
    const int va_m  = (tid & 3) * 8;
    const int pb_n  = tid >> 1;
    const int pb_h  = (tid & 1) * 16;

    for (int m0 = 0; m0 < Mm; m0 += 32) {
        // V tile (transposed store, split): As[m][d] = v[(d*4+h)][m0+m]
        {
            const float* vp = v + (size_t)(va_d * Hh + h) * Mm + m0 + va_m;
            #pragma unroll
            for (int qq = 0; qq < 2; qq++) {
                float4 v4 = *(const float4*)(vp + qq * 4);
                int ml = va_m + qq * 4;
                uint32_t hh, ll;
                split_tf32(v4.x, hh, ll); AsH[ml+0][va_d]=hh; AsL[ml+0][va_d]=ll;
                split_tf32(v4.y, hh, ll); AsH[ml+1][va_d]=hh; AsL[ml+1][va_d]=ll;
                split_tf32(v4.z, hh, ll); AsH[ml+2][va_d]=hh; AsL[ml+2][va_d]=ll;
                split_tf32(v4.w, hh, ll); AsH[ml+3][va_d]=hh; AsL[ml+3][va_d]=ll;
            }
        }
        // P tile (transposed store, split): Bs[m][n] = P[n0+n][m0+m]
        {
            const float* pp = P + (size_t)(n0 + pb_n) * Mm + m0 + pb_h;
            #pragma unroll
            for (int qq = 0; qq < 4; qq++) {
                float4 v4 = *(const float4*)(pp + qq * 4);
                int ml = pb_h + qq * 4;
                uint32_t hh, ll;
                split_tf32(v4.x, hh, ll); BsH[ml+0][pb_n]=hh; BsL[ml+0][pb_n]=ll;
                split_tf32(v4.y, hh, ll); BsH[ml+1][pb_n]=hh; BsL[ml+1][pb_n]=ll;
                split_tf32(v4.z, hh, ll); BsH[ml+2][pb_n]=hh; BsL[ml+2][pb_n]=ll;
                split_tf32(v4.w, hh, ll); BsH[ml+3][pb_n]=hh; BsL[ml+3][pb_n]=ll;
            }
        }
        __syncthreads();

        #pragma unroll
        for (int ks = 0; ks < 4; ks++) {
            const int kb = ks * 8;
            uint32_t ah[2][4], al[2][4], bh2[4][2], bl2[4][2];
            #pragma unroll
            for (int mt = 0; mt < 2; mt++) {
                int d = warp_m * 32 + mt * 16;
                ah[mt][0]=AsH[kb+tg  ][d+g  ]; al[mt][0]=AsL[kb+tg  ][d+g  ];
                ah[mt][1]=AsH[kb+tg  ][d+g+8]; al[mt][1]=AsL[kb+tg  ][d+g+8];
                ah[mt][2]=AsH[kb+tg+4][d+g  ]; al[mt][2]=AsL[kb+tg+4][d+g  ];
                ah[mt][3]=AsH[kb+tg+4][d+g+8]; al[mt][3]=AsL[kb+tg+4][d+g+8];
            }
            #pragma unroll
            for (int nt = 0; nt < 4; nt++) {
                int n = warp_n * 32 + nt * 8 + g;
                bh2[nt][0]=BsH[kb+tg  ][n]; bl2[nt][0]=BsL[kb+tg  ][n];
                bh2[nt][1]=BsH[kb+tg+4][n]; bl2[nt][1]=BsL[kb+tg+4][n];
            }
            #pragma unroll
            for (int mt = 0; mt < 2; mt++)
                #pragma unroll
                for (int nt = 0; nt < 4; nt++)
                    mma3(acc[mt][nt], ah[mt], al[mt], bh2[nt], bl2[nt]);
        }
        __syncthreads();
    }

    float* mp = g_msg + (size_t)b * Dd * Nn;
    #pragma unroll
    for (int mt = 0; mt < 2; mt++) {
        int d0 = warp_m * 32 + mt * 16 + g;
        int d1 = d0 + 8;
        #pragma unroll
        for (int nt = 0; nt < 4; nt++) {
            int n = n0 + warp_n * 32 + nt * 8 + 2 * tg;
            *(float2*)&mp[(size_t)(d0 * Hh + h) * Nn + n] =
                make_float2(acc[mt][nt][0], acc[mt][nt][1]);
            *(float2*)&mp[(size_t)(d1 * Hh + h) * Nn + n] =
                make_float2(acc[mt][nt][2], acc[mt][nt][3]);
        }
    }
}

// ---------------------------------------------------------------------------
extern "C" void kernel_launch(void* const* d_in, const int* in_sizes, int n_in,
                              void* d_out, int out_size)
{
    const float* x      = (const float*)d_in[0];
    const float* source = (const float*)d_in[1];
    const float* mask   = (const float*)d_in[2];
    const float* Wq = (const float*)d_in[3];
    const float* bq = (const float*)d_in[4];
    const float* Wk = (const float*)d_in[5];
    const float* bk = (const float*)d_in[6];
    const float* Wv = (const float*)d_in[7];
    const float* bv = (const float*)d_in[8];
    const float* Wm = (const float*)d_in[9];
    const float* bm = (const float*)d_in[10];
    const float* W1 = (const float*)d_in[11];
    const float* b1 = (const float*)d_in[12];
    const float* gamma = (const float*)d_in[13];
    const float* beta  = (const float*)d_in[14];
    const float* rmean = (const float*)d_in[15];
    const float* rvar  = (const float*)d_in[16];
    const float* W2 = (const float*)d_in[17];
    const float* b2 = (const float*)d_in[18];
    float* out = (float*)d_out;

    float *qb, *kb, *vb, *msgb, *messageb, *hb;
    cudaGetSymbolAddress((void**)&qb, g_q);
    cudaGetSymbolAddress((void**)&kb, g_k);
    cudaGetSymbolAddress((void**)&vb, g_v);
    cudaGetSymbolAddress((void**)&msgb, g_msg);
    cudaGetSymbolAddress((void**)&messageb, g_message);
    cudaGetSymbolAddress((void**)&hb, g_h);

    const int SMEM_GEMM   = 4 * 32 * SM_STRIDE * 4;                       // 69632
    const int SMEM_SCORES = 4 * 32 * SM_STRIDE * 4;                       // 69632
    const int SMEM_PV     = (64 * PV_STRIDE + 64 * SM_STRIDE) * 4;        // 53248

    cudaFuncSetAttribute(gemm_mma<256, 256, false, false>,
                         cudaFuncAttributeMaxDynamicSharedMemorySize, SMEM_GEMM);
    cudaFuncSetAttribute(gemm_mma<512, 512, true, true>,
                         cudaFuncAttributeMaxDynamicSharedMemorySize, SMEM_GEMM);
    cudaFuncSetAttribute(gemm_mma<256, 512, false, false>,
                         cudaFuncAttributeMaxDynamicSharedMemorySize, SMEM_GEMM);
    cudaFuncSetAttribute(attn_scores_mma,
                         cudaFuncAttributeMaxDynamicSharedMemorySize, SMEM_SCORES);
    cudaFuncSetAttribute(attn_pv_mma,
                         cudaFuncAttributeMaxDynamicSharedMemorySize, SMEM_PV);

    // q, k, v projections
    gemm_mma<256, 256, false, false><<<dim3(16, 2, 4), 256, SMEM_GEMM>>>(
        Wq, bq, x, nullptr, qb, nullptr, nullptr, nullptr, nullptr);
    gemm_mma<256, 256, false, false><<<dim3(16, 2, 4), 256, SMEM_GEMM>>>(
        Wk, bk, source, nullptr, kb, nullptr, nullptr, nullptr, nullptr);
    gemm_mma<256, 256, false, false><<<dim3(16, 2, 4), 256, SMEM_GEMM>>>(
        Wv, bv, source, nullptr, vb, nullptr, nullptr, nullptr, nullptr);

    // attention
    attn_scores_mma<<<dim3(16, 16, 16), 256, SMEM_SCORES>>>(mask);
    softmax_rows<<<Bn * Hh * Nn, 256>>>();
    attn_pv_mma<<<dim3(16, 1, 16), 256, SMEM_PV>>>();

    // message projection
    gemm_mma<256, 256, false, false><<<dim3(16, 2, 4), 256, SMEM_GEMM>>>(
        Wm, bm, msgb, nullptr, messageb, nullptr, nullptr, nullptr, nullptr);

    // MLP layer 1 (concat[x, message]) + BN + ReLU
    gemm_mma<512, 512, true, true><<<dim3(16, 4, 4), 256, SMEM_GEMM>>>(
        W1, b1, x, messageb, hb, gamma, beta, rmean, rvar);

    // MLP layer 2 -> output
    gemm_mma<256, 512, false, false><<<dim3(16, 2, 4), 256, SMEM_GEMM>>>(
        W2, b2, hb, nullptr, out, nullptr, nullptr, nullptr, nullptr);
}